// round 8
// baseline (speedup 1.0000x reference)
#include <cuda_runtime.h>
#include <math.h>

// ---------------- problem constants ----------------
#define B_   8
#define T_   1024
#define C_   768
#define H_   12
#define HS_  64
#define E_   8
#define F_   3072
#define N_   (B_*T_)     // 8192 tokens
#define BH_  (B_*H_)     // 96
#define C3_  (3*C_)      // 2304

// ---------------- scratch (device globals; no allocation) ----------------
__device__ float g_h1  [N_*C_];
__device__ float g_qkv [N_*C3_];
__device__ float g_S   [(size_t)BH_*T_*T_];   // 402 MB scores/probs (in-place softmax)
__device__ float g_o   [N_*C_];
__device__ float g_h2  [N_*C_];
__device__ float g_mid1[N_*F_];
__device__ float g_mid2[N_*F_];
__device__ float g_Y   [N_*C_];
__device__ float g_Wqkv[C_*C3_];
__device__ int   g_cnt [E_];
__device__ int   g_tok [E_*N_];
__device__ float g_gw  [E_*N_];

// ---------------- helpers ----------------
__device__ __forceinline__ float gelu_f(float z) {
    return 0.5f * z * (1.0f + erff(z * 0.70710678118654752440f));
}

// block-wide sum for 256 threads (8 warps)
__device__ __forceinline__ float blockReduceSum256(float v) {
    __shared__ float sh[8];
    int lane = threadIdx.x & 31, w = threadIdx.x >> 5;
    #pragma unroll
    for (int o = 16; o; o >>= 1) v += __shfl_down_sync(0xffffffffu, v, o);
    if (lane == 0) sh[w] = v;
    __syncthreads();
    float r;
    if (w == 0) {
        float t = (lane < 8) ? sh[lane] : 0.f;
        #pragma unroll
        for (int o = 4; o; o >>= 1) t += __shfl_down_sync(0xffffffffu, t, o);
        if (lane == 0) sh[0] = t;
    }
    __syncthreads();
    r = sh[0];
    __syncthreads();   // protect sh reuse by a following call
    return r;
}

// ---------------- small setup kernels ----------------
__global__ void zero_cnt_kernel(int* cnt) {
    if (threadIdx.x < E_) cnt[threadIdx.x] = 0;
}

// pack wq,wk,wv (H,C,HS) -> Wqkv[C][3C] with col = which*C + h*HS + d
__global__ void pack_wqkv_kernel(const float* __restrict__ wq,
                                 const float* __restrict__ wk,
                                 const float* __restrict__ wv) {
    int idx = blockIdx.x * 256 + threadIdx.x;
    if (idx >= C_ * C3_) return;
    int c   = idx / C3_;
    int col = idx - c * C3_;
    int which = col / C_;
    int rem   = col - which * C_;
    int h = rem / HS_;
    int d = rem - h * HS_;
    const float* w = (which == 0) ? wq : ((which == 1) ? wk : wv);
    g_Wqkv[idx] = w[(h * C_ + c) * HS_ + d];
}

// LayerNorm over C=768 (one row per block, 256 threads x 3 elems)
__global__ __launch_bounds__(256) void ln_kernel(const float* __restrict__ in,
                                                 const float* __restrict__ g,
                                                 const float* __restrict__ b,
                                                 float* __restrict__ out) {
    int row = blockIdx.x;
    const float* p = in + (size_t)row * C_;
    int t = threadIdx.x;
    float x0 = p[t], x1 = p[t + 256], x2 = p[t + 512];
    float mean = blockReduceSum256(x0 + x1 + x2) * (1.0f / C_);
    float d0 = x0 - mean, d1 = x1 - mean, d2 = x2 - mean;
    float var = blockReduceSum256(d0*d0 + d1*d1 + d2*d2) * (1.0f / C_);
    float rstd = rsqrtf(var + 1e-5f);
    float* o = out + (size_t)row * C_;
    o[t]       = d0 * rstd * g[t]       + b[t];
    o[t + 256] = d1 * rstd * g[t + 256] + b[t + 256];
    o[t + 512] = d2 * rstd * g[t + 512] + b[t + 512];
}

// ---------------- generic tiled SGEMM ----------------
// C[m,n] = act(A[m,:] @ B[:,n] + bias[n]) (+ resid[m,n])
// GATHER: A row index taken from rows[m]; cntPtr (if non-null) overrides M.
template<bool GATHER, int ACT, bool RESID>
__global__ __launch_bounds__(256) void sgemm_k(
    const float* __restrict__ A, int lda,
    const float* __restrict__ Bm,
    const float* __restrict__ bias,
    const float* __restrict__ resid,
    float* __restrict__ Cm, int ldc,
    int M, int Nn, int Kk,
    const int* __restrict__ rows,
    const int* __restrict__ cntPtr)
{
    if (cntPtr) M = *cntPtr;
    int m0 = blockIdx.y * 64;
    if (m0 >= M) return;
    int n0 = blockIdx.x * 64;

    __shared__ float As[16][65];
    __shared__ float Bs[16][64];
    __shared__ int   rIdx[64];

    int tid = threadIdx.x;
    if (GATHER) {
        if (tid < 64) {
            int m = m0 + tid;
            rIdx[tid] = rows[(m < M) ? m : (M - 1)];
        }
        __syncthreads();
    }

    int ty = tid >> 4, tx = tid & 15;
    int rowBase = ty * 4, colBase = tx * 4;
    float acc[4][4] = {};

    for (int k0 = 0; k0 < Kk; k0 += 16) {
        #pragma unroll
        for (int l = 0; l < 4; l++) {
            int idx = tid + l * 256;
            int r  = idx >> 4;
            int kk = idx & 15;
            int ar;
            if (GATHER) ar = rIdx[r];
            else { int gm = m0 + r; ar = (gm < M) ? gm : (M - 1); }
            As[kk][r] = A[(size_t)ar * lda + k0 + kk];
        }
        #pragma unroll
        for (int l = 0; l < 4; l++) {
            int idx = tid + l * 256;
            int kk = idx >> 6;
            int c  = idx & 63;
            Bs[kk][c] = Bm[(size_t)(k0 + kk) * Nn + n0 + c];
        }
        __syncthreads();
        #pragma unroll
        for (int kk = 0; kk < 16; kk++) {
            float a0 = As[kk][rowBase + 0];
            float a1 = As[kk][rowBase + 1];
            float a2 = As[kk][rowBase + 2];
            float a3 = As[kk][rowBase + 3];
            float4 bv = *reinterpret_cast<const float4*>(&Bs[kk][colBase]);
            acc[0][0] = fmaf(a0, bv.x, acc[0][0]); acc[0][1] = fmaf(a0, bv.y, acc[0][1]);
            acc[0][2] = fmaf(a0, bv.z, acc[0][2]); acc[0][3] = fmaf(a0, bv.w, acc[0][3]);
            acc[1][0] = fmaf(a1, bv.x, acc[1][0]); acc[1][1] = fmaf(a1, bv.y, acc[1][1]);
            acc[1][2] = fmaf(a1, bv.z, acc[1][2]); acc[1][3] = fmaf(a1, bv.w, acc[1][3]);
            acc[2][0] = fmaf(a2, bv.x, acc[2][0]); acc[2][1] = fmaf(a2, bv.y, acc[2][1]);
            acc[2][2] = fmaf(a2, bv.z, acc[2][2]); acc[2][3] = fmaf(a2, bv.w, acc[2][3]);
            acc[3][0] = fmaf(a3, bv.x, acc[3][0]); acc[3][1] = fmaf(a3, bv.y, acc[3][1]);
            acc[3][2] = fmaf(a3, bv.z, acc[3][2]); acc[3][3] = fmaf(a3, bv.w, acc[3][3]);
        }
        __syncthreads();
    }

    #pragma unroll
    for (int i = 0; i < 4; i++) {
        int m = m0 + rowBase + i;
        if (m >= M) continue;
        #pragma unroll
        for (int j = 0; j < 4; j++) {
            int n = n0 + colBase + j;
            float v = acc[i][j];
            if (bias) v += bias[n];
            if (ACT == 1) v = gelu_f(v);
            if (RESID) v += resid[(size_t)m * ldc + n];
            Cm[(size_t)m * ldc + n] = v;
        }
    }
}

// ---------------- attention ----------------
// raw scores S[bh][t][s] = (q.k) * C^-0.5 ; skip fully-masked tiles
__global__ __launch_bounds__(256) void attn_scores_kernel(const float* __restrict__ qkv,
                                                          float* __restrict__ S) {
    int bh = blockIdx.z;
    int t0 = blockIdx.y * 64, s0 = blockIdx.x * 64;
    if (s0 > t0) return;                   // whole tile above diagonal
    int b = bh / H_, h = bh - b * H_;

    __shared__ float Qs[64][65];           // [d][t]
    __shared__ float Ks[64][65];           // [d][s]
    int tid = threadIdx.x;
    const float* qb = qkv + (size_t)(b * T_ + t0) * C3_ + h * HS_;
    const float* kb = qkv + (size_t)(b * T_ + s0) * C3_ + C_ + h * HS_;
    #pragma unroll
    for (int l = 0; l < 16; l++) {
        int idx = tid + l * 256;
        int r = idx >> 6, d = idx & 63;
        Qs[d][r] = qb[(size_t)r * C3_ + d];
        Ks[d][r] = kb[(size_t)r * C3_ + d];
    }
    __syncthreads();

    int ty = tid >> 4, tx = tid & 15;
    int tb = ty * 4, sb = tx * 4;
    float acc[4][4] = {};
    #pragma unroll 16
    for (int d = 0; d < 64; d++) {
        float a0 = Qs[d][tb+0], a1 = Qs[d][tb+1], a2 = Qs[d][tb+2], a3 = Qs[d][tb+3];
        float b0 = Ks[d][sb+0], b1 = Ks[d][sb+1], b2 = Ks[d][sb+2], b3 = Ks[d][sb+3];
        acc[0][0]=fmaf(a0,b0,acc[0][0]); acc[0][1]=fmaf(a0,b1,acc[0][1]); acc[0][2]=fmaf(a0,b2,acc[0][2]); acc[0][3]=fmaf(a0,b3,acc[0][3]);
        acc[1][0]=fmaf(a1,b0,acc[1][0]); acc[1][1]=fmaf(a1,b1,acc[1][1]); acc[1][2]=fmaf(a1,b2,acc[1][2]); acc[1][3]=fmaf(a1,b3,acc[1][3]);
        acc[2][0]=fmaf(a2,b0,acc[2][0]); acc[2][1]=fmaf(a2,b1,acc[2][1]); acc[2][2]=fmaf(a2,b2,acc[2][2]); acc[2][3]=fmaf(a2,b3,acc[2][3]);
        acc[3][0]=fmaf(a3,b0,acc[3][0]); acc[3][1]=fmaf(a3,b1,acc[3][1]); acc[3][2]=fmaf(a3,b2,acc[3][2]); acc[3][3]=fmaf(a3,b3,acc[3][3]);
    }
    const float scale = 0.03608439182435161f;   // 768^-0.5
    float* op = S + ((size_t)bh * T_ + t0) * T_ + s0;
    #pragma unroll
    for (int i = 0; i < 4; i++)
        #pragma unroll
        for (int j = 0; j < 4; j++)
            op[(size_t)(tb + i) * T_ + sb + j] = acc[i][j] * scale;
}

// causal softmax in place: reads only s<=t, zeros s>t
__global__ __launch_bounds__(128) void softmax_causal_kernel(float* __restrict__ S) {
    int row = blockIdx.x;                 // bh*T + t
    int t = row & (T_ - 1);
    float* p = S + (size_t)row * T_;
    int len = t + 1;
    int tid = threadIdx.x;
    __shared__ float sh[4];

    float mx = -1e30f;
    for (int s = tid; s < len; s += 128) mx = fmaxf(mx, p[s]);
    #pragma unroll
    for (int o = 16; o; o >>= 1) mx = fmaxf(mx, __shfl_down_sync(0xffffffffu, mx, o));
    if ((tid & 31) == 0) sh[tid >> 5] = mx;
    __syncthreads();
    mx = fmaxf(fmaxf(sh[0], sh[1]), fmaxf(sh[2], sh[3]));
    __syncthreads();

    float sum = 0.f;
    for (int s = tid; s < len; s += 128) { float e = __expf(p[s] - mx); p[s] = e; sum += e; }
    #pragma unroll
    for (int o = 16; o; o >>= 1) sum += __shfl_down_sync(0xffffffffu, sum, o);
    if ((tid & 31) == 0) sh[tid >> 5] = sum;
    __syncthreads();
    sum = sh[0] + sh[1] + sh[2] + sh[3];
    float inv = 1.f / sum;
    for (int s = tid; s < len; s += 128) p[s] *= inv;
    for (int s = len + tid; s < T_; s += 128) p[s] = 0.f;
}

// O = P @ V ; skips K-tiles that are all-zero (s0 > t)
__global__ __launch_bounds__(256) void attn_pv_kernel(const float* __restrict__ qkv,
                                                      const float* __restrict__ P,
                                                      float* __restrict__ O) {
    int bh = blockIdx.y;
    int b = bh / H_, h = bh - b * H_;
    int t0 = blockIdx.x * 64;

    __shared__ float Ps[64][65];          // [s][t]
    __shared__ float Vs[64][65];          // [s][d]
    int tid = threadIdx.x;
    int ty = tid >> 4, tx = tid & 15;
    int tb = ty * 4, db = tx * 4;
    float acc[4][4] = {};
    const float* prow = P + ((size_t)bh * T_ + t0) * T_;

    for (int s0 = 0; s0 <= t0; s0 += 64) {
        #pragma unroll
        for (int l = 0; l < 16; l++) {
            int idx = tid + l * 256;
            int a_ = idx >> 6, b_ = idx & 63;
            Ps[b_][a_] = prow[(size_t)a_ * T_ + s0 + b_];
            Vs[a_][b_] = qkv[(size_t)(b * T_ + s0 + a_) * C3_ + 2 * C_ + h * HS_ + b_];
        }
        __syncthreads();
        #pragma unroll 16
        for (int s = 0; s < 64; s++) {
            float a0 = Ps[s][tb+0], a1 = Ps[s][tb+1], a2 = Ps[s][tb+2], a3 = Ps[s][tb+3];
            float b0 = Vs[s][db+0], b1 = Vs[s][db+1], b2 = Vs[s][db+2], b3 = Vs[s][db+3];
            acc[0][0]=fmaf(a0,b0,acc[0][0]); acc[0][1]=fmaf(a0,b1,acc[0][1]); acc[0][2]=fmaf(a0,b2,acc[0][2]); acc[0][3]=fmaf(a0,b3,acc[0][3]);
            acc[1][0]=fmaf(a1,b0,acc[1][0]); acc[1][1]=fmaf(a1,b1,acc[1][1]); acc[1][2]=fmaf(a1,b2,acc[1][2]); acc[1][3]=fmaf(a1,b3,acc[1][3]);
            acc[2][0]=fmaf(a2,b0,acc[2][0]); acc[2][1]=fmaf(a2,b1,acc[2][1]); acc[2][2]=fmaf(a2,b2,acc[2][2]); acc[2][3]=fmaf(a2,b3,acc[2][3]);
            acc[3][0]=fmaf(a3,b0,acc[3][0]); acc[3][1]=fmaf(a3,b1,acc[3][1]); acc[3][2]=fmaf(a3,b2,acc[3][2]); acc[3][3]=fmaf(a3,b3,acc[3][3]);
        }
        __syncthreads();
    }
    #pragma unroll
    for (int i = 0; i < 4; i++)
        #pragma unroll
        for (int j = 0; j < 4; j++)
            O[(size_t)(b * T_ + t0 + tb + i) * C_ + h * HS_ + db + j] = acc[i][j];
}

// ---------------- router: noisy top-2 + assignment (one warp / token) ----------------
__global__ __launch_bounds__(256) void router_kernel(
    const float* __restrict__ h2,
    const float* __restrict__ wr, const float* __restrict__ br,
    const float* __restrict__ wn, const float* __restrict__ bn,
    const float* __restrict__ noise, const float* __restrict__ temp_p,
    int* __restrict__ cnt, int* __restrict__ tok, float* __restrict__ gw)
{
    int n = blockIdx.x * 8 + (threadIdx.x >> 5);
    if (n >= N_) return;
    int lane = threadIdx.x & 31;
    float ar[E_] = {}, an[E_] = {};
    const float* hp = h2 + (size_t)n * C_;
    for (int c = lane; c < C_; c += 32) {
        float hv = hp[c];
        const float* wrp = wr + c * E_;
        const float* wnp = wn + c * E_;
        #pragma unroll
        for (int e = 0; e < E_; e++) {
            ar[e] = fmaf(hv, wrp[e], ar[e]);
            an[e] = fmaf(hv, wnp[e], an[e]);
        }
    }
    #pragma unroll
    for (int e = 0; e < E_; e++) {
        #pragma unroll
        for (int o = 16; o; o >>= 1) {
            ar[e] += __shfl_down_sync(0xffffffffu, ar[e], o);
            an[e] += __shfl_down_sync(0xffffffffu, an[e], o);
        }
    }
    if (lane == 0) {
        float t = fminf(fmaxf(*temp_p, 0.5f), 2.0f);
        float noisy[E_];
        #pragma unroll
        for (int e = 0; e < E_; e++) {
            float logit = ar[e] + br[e];
            float z = an[e] + bn[e];
            float sp = fmaxf(z, 0.f) + log1pf(expf(-fabsf(z)));  // softplus
            noisy[e] = logit + t * noise[(size_t)n * E_ + e] * sp;
        }
        int i1 = 0;
        #pragma unroll
        for (int e = 1; e < E_; e++) if (noisy[e] > noisy[i1]) i1 = e;
        int i2 = -1;
        #pragma unroll
        for (int e = 0; e < E_; e++)
            if (e != i1 && (i2 < 0 || noisy[e] > noisy[i2])) i2 = e;
        float m = fmaxf(noisy[i1], noisy[i2]);
        float e1 = __expf(noisy[i1] - m), e2 = __expf(noisy[i2] - m);
        float inv = 1.f / (e1 + e2);
        int p1 = atomicAdd(&cnt[i1], 1); tok[i1 * N_ + p1] = n; gw[i1 * N_ + p1] = e1 * inv;
        int p2 = atomicAdd(&cnt[i2], 1); tok[i2 * N_ + p2] = n; gw[i2 * N_ + p2] = e2 * inv;
    }
}

// ---------------- expert epilogue: out[n] += gate * LN(h2[n] + Y[m]) ----------------
__global__ __launch_bounds__(256) void expert_epi_kernel(
    const float* __restrict__ Y, const float* __restrict__ h2,
    const int* __restrict__ tok, const float* __restrict__ gw,
    const int* __restrict__ cnt,
    const float* __restrict__ lg, const float* __restrict__ lb,
    float* __restrict__ out)
{
    int m = blockIdx.x;
    if (m >= *cnt) return;
    int n = tok[m];
    float g = gw[m];
    const float* yp = Y + (size_t)m * C_;
    const float* hp = h2 + (size_t)n * C_;
    int t = threadIdx.x;
    float z0 = hp[t]       + yp[t];
    float z1 = hp[t + 256] + yp[t + 256];
    float z2 = hp[t + 512] + yp[t + 512];
    float mean = blockReduceSum256(z0 + z1 + z2) * (1.0f / C_);
    float d0 = z0 - mean, d1 = z1 - mean, d2 = z2 - mean;
    float var = blockReduceSum256(d0*d0 + d1*d1 + d2*d2) * (1.0f / C_);
    float rstd = rsqrtf(var + 1e-5f);
    float* op = out + (size_t)n * C_;
    op[t]       += g * (d0 * rstd * lg[t]       + lb[t]);
    op[t + 256] += g * (d1 * rstd * lg[t + 256] + lb[t + 256]);
    op[t + 512] += g * (d2 * rstd * lg[t + 512] + lb[t + 512]);
}

// ---------------- launch ----------------
extern "C" void kernel_launch(void* const* d_in, const int* in_sizes, int n_in,
                              void* d_out, int out_size) {
    const float* x         = (const float*)d_in[0];
    const float* rnoise    = (const float*)d_in[1];
    const float* wq        = (const float*)d_in[2];
    const float* wk        = (const float*)d_in[3];
    const float* wv        = (const float*)d_in[4];
    const float* w_proj    = (const float*)d_in[5];
    const float* b_proj    = (const float*)d_in[6];
    const float* ln1_g     = (const float*)d_in[7];
    const float* ln1_b     = (const float*)d_in[8];
    const float* ln2_g     = (const float*)d_in[9];
    const float* ln2_b     = (const float*)d_in[10];
    const float* w_route   = (const float*)d_in[11];
    const float* b_route   = (const float*)d_in[12];
    const float* w_noise   = (const float*)d_in[13];
    const float* b_noise   = (const float*)d_in[14];
    const float* temp      = (const float*)d_in[15];
    const float* deep_w1   = (const float*)d_in[16];
    const float* deep_b1   = (const float*)d_in[17];
    const float* deep_w2   = (const float*)d_in[18];
    const float* deep_b2   = (const float*)d_in[19];
    const float* deep_w3   = (const float*)d_in[20];
    const float* deep_b3   = (const float*)d_in[21];
    const float* deep_ln_g = (const float*)d_in[22];
    const float* deep_ln_b = (const float*)d_in[23];
    const float* simple_w1   = (const float*)d_in[24];
    const float* simple_b1   = (const float*)d_in[25];
    const float* simple_w2   = (const float*)d_in[26];
    const float* simple_b2   = (const float*)d_in[27];
    const float* simple_ln_g = (const float*)d_in[28];
    const float* simple_ln_b = (const float*)d_in[29];

    float* out = (float*)d_out;

    float *h1, *qkv, *S, *o, *h2, *mid1, *mid2, *Y, *Wqkv, *gw;
    int *cnt, *tok;
    cudaGetSymbolAddress((void**)&h1,   g_h1);
    cudaGetSymbolAddress((void**)&qkv,  g_qkv);
    cudaGetSymbolAddress((void**)&S,    g_S);
    cudaGetSymbolAddress((void**)&o,    g_o);
    cudaGetSymbolAddress((void**)&h2,   g_h2);
    cudaGetSymbolAddress((void**)&mid1, g_mid1);
    cudaGetSymbolAddress((void**)&mid2, g_mid2);
    cudaGetSymbolAddress((void**)&Y,    g_Y);
    cudaGetSymbolAddress((void**)&Wqkv, g_Wqkv);
    cudaGetSymbolAddress((void**)&cnt,  g_cnt);
    cudaGetSymbolAddress((void**)&tok,  g_tok);
    cudaGetSymbolAddress((void**)&gw,   g_gw);

    zero_cnt_kernel<<<1, 32>>>(cnt);
    pack_wqkv_kernel<<<(C_ * C3_ + 255) / 256, 256>>>(wq, wk, wv);

    // ln1 -> h1 ; qkv = h1 @ Wqkv
    ln_kernel<<<N_, 256>>>(x, ln1_g, ln1_b, h1);
    sgemm_k<false, 0, false><<<dim3(C3_ / 64, N_ / 64), 256>>>(
        h1, C_, Wqkv, nullptr, nullptr, qkv, C3_, N_, C3_, C_, nullptr, nullptr);

    // attention
    attn_scores_kernel<<<dim3(T_ / 64, T_ / 64, BH_), 256>>>(qkv, S);
    softmax_causal_kernel<<<BH_ * T_, 128>>>(S);
    attn_pv_kernel<<<dim3(T_ / 64, BH_), 256>>>(qkv, S, o);

    // out = x + o @ w_proj + b_proj   (out also serves as residual base x1)
    sgemm_k<false, 0, true><<<dim3(C_ / 64, N_ / 64), 256>>>(
        o, C_, w_proj, b_proj, x, out, C_, N_, C_, C_, nullptr, nullptr);

    // ln2 -> h2 ; router + token assignment
    ln_kernel<<<N_, 256>>>(out, ln2_g, ln2_b, h2);
    router_kernel<<<N_ / 8, 256>>>(h2, w_route, b_route, w_noise, b_noise,
                                   rnoise, temp, cnt, tok, gw);

    // deep experts (0..1): gelu(W1) -> gelu(W2) -> W3 -> LN accumulate
    for (int e = 0; e < 2; e++) {
        const int*   ce = cnt + e;
        const int*   te = tok + e * N_;
        const float* ge = gw + e * N_;
        sgemm_k<true, 1, false><<<dim3(F_ / 64, N_ / 64), 256>>>(
            h2, C_, deep_w1 + (size_t)e * C_ * F_, deep_b1 + (size_t)e * F_,
            nullptr, mid1, F_, N_, F_, C_, te, ce);
        sgemm_k<false, 1, false><<<dim3(F_ / 64, N_ / 64), 256>>>(
            mid1, F_, deep_w2 + (size_t)e * F_ * F_, deep_b2 + (size_t)e * F_,
            nullptr, mid2, F_, N_, F_, F_, nullptr, ce);
        sgemm_k<false, 0, false><<<dim3(C_ / 64, N_ / 64), 256>>>(
            mid2, F_, deep_w3 + (size_t)e * F_ * C_, deep_b3 + (size_t)e * C_,
            nullptr, Y, C_, N_, C_, F_, nullptr, ce);
        expert_epi_kernel<<<N_, 256>>>(Y, h2, te, ge, ce,
                                       deep_ln_g + (size_t)e * C_,
                                       deep_ln_b + (size_t)e * C_, out);
    }

    // simple experts (2..7): gelu(W1) -> W2 -> LN accumulate
    for (int e = 0; e < 6; e++) {
        int ee = 2 + e;
        const int*   ce = cnt + ee;
        const int*   te = tok + ee * N_;
        const float* ge = gw + ee * N_;
        sgemm_k<true, 1, false><<<dim3(F_ / 64, N_ / 64), 256>>>(
            h2, C_, simple_w1 + (size_t)e * C_ * F_, simple_b1 + (size_t)e * F_,
            nullptr, mid1, F_, N_, F_, C_, te, ce);
        sgemm_k<false, 0, false><<<dim3(C_ / 64, N_ / 64), 256>>>(
            mid1, F_, simple_w2 + (size_t)e * F_ * C_, simple_b2 + (size_t)e * C_,
            nullptr, Y, C_, N_, C_, F_, nullptr, ce);
        expert_epi_kernel<<<N_, 256>>>(Y, h2, te, ge, ce,
                                       simple_ln_g + (size_t)e * C_,
                                       simple_ln_b + (size_t)e * C_, out);
    }
}

// round 9
// speedup vs baseline: 2.4202x; 2.4202x over previous
#include <cuda_runtime.h>
#include <math.h>

// ---------------- problem constants ----------------
#define B_   8
#define T_   1024
#define C_   768
#define H_   12
#define HS_  64
#define E_   8
#define F_   3072
#define N_   (B_*T_)     // 8192 tokens
#define BH_  (B_*H_)     // 96
#define C3_  (3*C_)      // 2304

// ---------------- scratch (device globals; no allocation) ----------------
__device__ float g_h1  [N_*C_];
__device__ float g_qkv [N_*C3_];
__device__ float g_S   [(size_t)BH_*T_*T_];   // 402 MB scores/probs (in-place softmax)
__device__ float g_o   [N_*C_];
__device__ float g_h2  [N_*C_];
__device__ float g_mid1[N_*F_];
__device__ float g_mid2[N_*F_];
__device__ float g_Y   [N_*C_];
__device__ float g_Wqkv[C_*C3_];
__device__ int   g_cnt [E_];
__device__ int   g_tok [E_*N_];
__device__ float g_gw  [E_*N_];

// ---------------- helpers ----------------
__device__ __forceinline__ float gelu_f(float z) {
    return 0.5f * z * (1.0f + erff(z * 0.70710678118654752440f));
}

__device__ __forceinline__ unsigned f2tf32(float f) {
    unsigned r;
    asm("cvt.rna.tf32.f32 %0, %1;" : "=r"(r) : "f"(f));
    return r;
}

__device__ __forceinline__ void ldsm4(unsigned &r0, unsigned &r1, unsigned &r2, unsigned &r3,
                                      const unsigned* p) {
    unsigned addr = (unsigned)__cvta_generic_to_shared(p);
    asm volatile("ldmatrix.sync.aligned.m8n8.x4.shared.b16 {%0,%1,%2,%3}, [%4];"
        : "=r"(r0), "=r"(r1), "=r"(r2), "=r"(r3) : "r"(addr));
}

__device__ __forceinline__ void mma_tf32(float* c, const unsigned* a, const unsigned* b) {
    asm volatile("mma.sync.aligned.m16n8k8.row.col.f32.tf32.tf32.f32 "
        "{%0,%1,%2,%3}, {%4,%5,%6,%7}, {%8,%9}, {%0,%1,%2,%3};"
        : "+f"(c[0]), "+f"(c[1]), "+f"(c[2]), "+f"(c[3])
        : "r"(a[0]), "r"(a[1]), "r"(a[2]), "r"(a[3]), "r"(b[0]), "r"(b[1]));
}

// block-wide sum for 256 threads (8 warps)
__device__ __forceinline__ float blockReduceSum256(float v) {
    __shared__ float sh[8];
    int lane = threadIdx.x & 31, w = threadIdx.x >> 5;
    #pragma unroll
    for (int o = 16; o; o >>= 1) v += __shfl_down_sync(0xffffffffu, v, o);
    if (lane == 0) sh[w] = v;
    __syncthreads();
    float r;
    if (w == 0) {
        float t = (lane < 8) ? sh[lane] : 0.f;
        #pragma unroll
        for (int o = 4; o; o >>= 1) t += __shfl_down_sync(0xffffffffu, t, o);
        if (lane == 0) sh[0] = t;
    }
    __syncthreads();
    r = sh[0];
    __syncthreads();
    return r;
}

// ---------------- small setup kernels ----------------
__global__ void zero_cnt_kernel(int* cnt) {
    if (threadIdx.x < E_) cnt[threadIdx.x] = 0;
}

// pack wq,wk,wv (H,C,HS) -> Wqkv[C][3C] with col = which*C + h*HS + d
__global__ void pack_wqkv_kernel(const float* __restrict__ wq,
                                 const float* __restrict__ wk,
                                 const float* __restrict__ wv) {
    int idx = blockIdx.x * 256 + threadIdx.x;
    if (idx >= C_ * C3_) return;
    int c   = idx / C3_;
    int col = idx - c * C3_;
    int which = col / C_;
    int rem   = col - which * C_;
    int h = rem / HS_;
    int d = rem - h * HS_;
    const float* w = (which == 0) ? wq : ((which == 1) ? wk : wv);
    g_Wqkv[idx] = w[(h * C_ + c) * HS_ + d];
}

// LayerNorm over C=768 (one row per block, 256 threads x 3 elems)
__global__ __launch_bounds__(256) void ln_kernel(const float* __restrict__ in,
                                                 const float* __restrict__ g,
                                                 const float* __restrict__ b,
                                                 float* __restrict__ out) {
    int row = blockIdx.x;
    const float* p = in + (size_t)row * C_;
    int t = threadIdx.x;
    float x0 = p[t], x1 = p[t + 256], x2 = p[t + 512];
    float mean = blockReduceSum256(x0 + x1 + x2) * (1.0f / C_);
    float d0 = x0 - mean, d1 = x1 - mean, d2 = x2 - mean;
    float var = blockReduceSum256(d0*d0 + d1*d1 + d2*d2) * (1.0f / C_);
    float rstd = rsqrtf(var + 1e-5f);
    float* o = out + (size_t)row * C_;
    o[t]       = d0 * rstd * g[t]       + b[t];
    o[t + 256] = d1 * rstd * g[t + 256] + b[t + 256];
    o[t + 512] = d2 * rstd * g[t + 512] + b[t + 512];
}

// ---------------- tf32 tensor-core GEMM ----------------
// C[m,n] = act(A[m,:] @ B[:,n] + bias[n]) (+ resid[m,n])
// Block tile 128x128x16, 8 warps (2x4), warp tile 64x32 via mma.m16n8k8 tf32.
// GATHER: A row index from rows[m]; cntPtr (if non-null) overrides M.
// Requires Nn % 128 == 0, Kk % 16 == 0.
template<bool GATHER, int ACT, bool RESID>
__global__ __launch_bounds__(256) void tgemm_k(
    const float* __restrict__ A, int lda,
    const float* __restrict__ Bm,
    const float* __restrict__ bias,
    const float* __restrict__ resid,
    float* __restrict__ Cm, int ldc,
    int M, int Nn, int Kk,
    const int* __restrict__ rows,
    const int* __restrict__ cntPtr)
{
    if (cntPtr) M = *cntPtr;
    int m0 = blockIdx.y * 128;
    if (m0 >= M) return;
    int n0 = blockIdx.x * 128;

    __shared__ unsigned As[2][128][20];   // [row][k], pad 20 -> conflict-free ldsm
    __shared__ unsigned Bs[2][16][136];   // [k][n],  pad 136 -> conflict-free LDS
    __shared__ int rIdx[128];

    int tid = threadIdx.x;
    if (GATHER) {
        if (tid < 128) {
            int m = m0 + tid;
            rIdx[tid] = rows[(m < M) ? m : (M - 1)];
        }
        __syncthreads();
    }

    // ---- gmem load mapping ----
    // A: thread loads row (tid&127), two float4 at k-cols aCol and aCol+8
    int aRow = tid & 127;
    int aCol = (tid >> 7) * 4;   // 0 or 4
    int aSrcRow;
    if (GATHER) aSrcRow = rIdx[aRow];
    else { int gm = m0 + aRow; aSrcRow = (gm < M) ? gm : (M - 1); }
    const float* aPtr = A + (size_t)aSrcRow * lda;
    // B: thread loads k-row (tid>>4), two float4 at n-cols bN and bN+64
    int bK = tid >> 4;
    int bN = (tid & 15) * 4;
    const float* bPtr = Bm + (size_t)bK * Nn + n0;

    float4 aV0, aV1, bV0, bV1;

    // ---- warp / fragment mapping ----
    int wid = tid >> 5, lane = tid & 31;
    int warpM = (wid >> 2) * 64;     // 0 or 64
    int warpN = (wid & 3) * 32;      // 0,32,64,96
    int g  = lane >> 2;              // groupID 0..7
    int tg = lane & 3;               // thread-in-group 0..3
    // per-thread ldmatrix address components (x4 tile decomposition)
    int aRowIn = ((lane >> 3) & 1) * 8 + (lane & 7);
    int aColIn = ((lane >> 3) >> 1) * 4;

    float acc[4][4][4];
    #pragma unroll
    for (int i = 0; i < 4; i++)
        #pragma unroll
        for (int j = 0; j < 4; j++)
            #pragma unroll
            for (int r = 0; r < 4; r++) acc[i][j][r] = 0.f;

    int nTiles = Kk / 16;

    // prologue: load tile 0 and stage it
    aV0 = *(const float4*)(aPtr + 0 + aCol);
    aV1 = *(const float4*)(aPtr + 0 + aCol + 8);
    bV0 = *(const float4*)(bPtr + 0 + bN);
    bV1 = *(const float4*)(bPtr + 0 + bN + 64);
    {
        uint4 u0 = { f2tf32(aV0.x), f2tf32(aV0.y), f2tf32(aV0.z), f2tf32(aV0.w) };
        uint4 u1 = { f2tf32(aV1.x), f2tf32(aV1.y), f2tf32(aV1.z), f2tf32(aV1.w) };
        *(uint4*)&As[0][aRow][aCol]     = u0;
        *(uint4*)&As[0][aRow][aCol + 8] = u1;
        uint4 v0 = { f2tf32(bV0.x), f2tf32(bV0.y), f2tf32(bV0.z), f2tf32(bV0.w) };
        uint4 v1 = { f2tf32(bV1.x), f2tf32(bV1.y), f2tf32(bV1.z), f2tf32(bV1.w) };
        *(uint4*)&Bs[0][bK][bN]      = v0;
        *(uint4*)&Bs[0][bK][bN + 64] = v1;
    }
    __syncthreads();

    for (int t = 0; t < nTiles; t++) {
        int buf = t & 1;
        bool more = (t + 1 < nTiles);
        if (more) {
            int k0 = (t + 1) * 16;
            aV0 = *(const float4*)(aPtr + k0 + aCol);
            aV1 = *(const float4*)(aPtr + k0 + aCol + 8);
            const float* bp = bPtr + (size_t)k0 * Nn;
            bV0 = *(const float4*)(bp + bN);
            bV1 = *(const float4*)(bp + bN + 64);
        }

        #pragma unroll
        for (int s = 0; s < 2; s++) {
            unsigned af[4][4];
            #pragma unroll
            for (int i = 0; i < 4; i++)
                ldsm4(af[i][0], af[i][1], af[i][2], af[i][3],
                      &As[buf][warpM + i * 16 + aRowIn][s * 8 + aColIn]);
            unsigned bf[4][2];
            #pragma unroll
            for (int j = 0; j < 4; j++) {
                int col = warpN + j * 8 + g;
                bf[j][0] = Bs[buf][s * 8 + tg][col];
                bf[j][1] = Bs[buf][s * 8 + tg + 4][col];
            }
            #pragma unroll
            for (int i = 0; i < 4; i++)
                #pragma unroll
                for (int j = 0; j < 4; j++)
                    mma_tf32(acc[i][j], af[i], bf[j]);
        }

        if (more) {
            int nb = buf ^ 1;
            uint4 u0 = { f2tf32(aV0.x), f2tf32(aV0.y), f2tf32(aV0.z), f2tf32(aV0.w) };
            uint4 u1 = { f2tf32(aV1.x), f2tf32(aV1.y), f2tf32(aV1.z), f2tf32(aV1.w) };
            *(uint4*)&As[nb][aRow][aCol]     = u0;
            *(uint4*)&As[nb][aRow][aCol + 8] = u1;
            uint4 v0 = { f2tf32(bV0.x), f2tf32(bV0.y), f2tf32(bV0.z), f2tf32(bV0.w) };
            uint4 v1 = { f2tf32(bV1.x), f2tf32(bV1.y), f2tf32(bV1.z), f2tf32(bV1.w) };
            *(uint4*)&Bs[nb][bK][bN]      = v0;
            *(uint4*)&Bs[nb][bK][bN + 64] = v1;
        }
        __syncthreads();
    }

    // ---- epilogue ----
    #pragma unroll
    for (int i = 0; i < 4; i++) {
        int r0 = m0 + warpM + i * 16 + g;
        int r1 = r0 + 8;
        #pragma unroll
        for (int j = 0; j < 4; j++) {
            int col = n0 + warpN + j * 8 + tg * 2;
            float b0 = 0.f, b1 = 0.f;
            if (bias) { b0 = bias[col]; b1 = bias[col + 1]; }
            if (r0 < M) {
                float v0 = acc[i][j][0] + b0;
                float v1 = acc[i][j][1] + b1;
                if (ACT == 1) { v0 = gelu_f(v0); v1 = gelu_f(v1); }
                if (RESID) {
                    v0 += resid[(size_t)r0 * ldc + col];
                    v1 += resid[(size_t)r0 * ldc + col + 1];
                }
                *(float2*)&Cm[(size_t)r0 * ldc + col] = make_float2(v0, v1);
            }
            if (r1 < M) {
                float v2 = acc[i][j][2] + b0;
                float v3 = acc[i][j][3] + b1;
                if (ACT == 1) { v2 = gelu_f(v2); v3 = gelu_f(v3); }
                if (RESID) {
                    v2 += resid[(size_t)r1 * ldc + col];
                    v3 += resid[(size_t)r1 * ldc + col + 1];
                }
                *(float2*)&Cm[(size_t)r1 * ldc + col] = make_float2(v2, v3);
            }
        }
    }
}

// ---------------- attention ----------------
// raw scores S[bh][t][s] = (q.k) * C^-0.5 ; skip fully-masked tiles
__global__ __launch_bounds__(256) void attn_scores_kernel(const float* __restrict__ qkv,
                                                          float* __restrict__ S) {
    int bh = blockIdx.z;
    int t0 = blockIdx.y * 64, s0 = blockIdx.x * 64;
    if (s0 > t0) return;
    int b = bh / H_, h = bh - b * H_;

    __shared__ float Qs[64][65];
    __shared__ float Ks[64][65];
    int tid = threadIdx.x;
    const float* qb = qkv + (size_t)(b * T_ + t0) * C3_ + h * HS_;
    const float* kb = qkv + (size_t)(b * T_ + s0) * C3_ + C_ + h * HS_;
    #pragma unroll
    for (int l = 0; l < 16; l++) {
        int idx = tid + l * 256;
        int r = idx >> 6, d = idx & 63;
        Qs[d][r] = qb[(size_t)r * C3_ + d];
        Ks[d][r] = kb[(size_t)r * C3_ + d];
    }
    __syncthreads();

    int ty = tid >> 4, tx = tid & 15;
    int tb = ty * 4, sb = tx * 4;
    float acc[4][4] = {};
    #pragma unroll 16
    for (int d = 0; d < 64; d++) {
        float a0 = Qs[d][tb+0], a1 = Qs[d][tb+1], a2 = Qs[d][tb+2], a3 = Qs[d][tb+3];
        float b0 = Ks[d][sb+0], b1 = Ks[d][sb+1], b2 = Ks[d][sb+2], b3 = Ks[d][sb+3];
        acc[0][0]=fmaf(a0,b0,acc[0][0]); acc[0][1]=fmaf(a0,b1,acc[0][1]); acc[0][2]=fmaf(a0,b2,acc[0][2]); acc[0][3]=fmaf(a0,b3,acc[0][3]);
        acc[1][0]=fmaf(a1,b0,acc[1][0]); acc[1][1]=fmaf(a1,b1,acc[1][1]); acc[1][2]=fmaf(a1,b2,acc[1][2]); acc[1][3]=fmaf(a1,b3,acc[1][3]);
        acc[2][0]=fmaf(a2,b0,acc[2][0]); acc[2][1]=fmaf(a2,b1,acc[2][1]); acc[2][2]=fmaf(a2,b2,acc[2][2]); acc[2][3]=fmaf(a2,b3,acc[2][3]);
        acc[3][0]=fmaf(a3,b0,acc[3][0]); acc[3][1]=fmaf(a3,b1,acc[3][1]); acc[3][2]=fmaf(a3,b2,acc[3][2]); acc[3][3]=fmaf(a3,b3,acc[3][3]);
    }
    const float scale = 0.03608439182435161f;   // 768^-0.5
    float* op = S + ((size_t)bh * T_ + t0) * T_ + s0;
    #pragma unroll
    for (int i = 0; i < 4; i++)
        #pragma unroll
        for (int j = 0; j < 4; j++)
            op[(size_t)(tb + i) * T_ + sb + j] = acc[i][j] * scale;
}

// causal softmax in place: reads only s<=t, zeros s>t
__global__ __launch_bounds__(128) void softmax_causal_kernel(float* __restrict__ S) {
    int row = blockIdx.x;
    int t = row & (T_ - 1);
    float* p = S + (size_t)row * T_;
    int len = t + 1;
    int tid = threadIdx.x;
    __shared__ float sh[4];

    float mx = -1e30f;
    for (int s = tid; s < len; s += 128) mx = fmaxf(mx, p[s]);
    #pragma unroll
    for (int o = 16; o; o >>= 1) mx = fmaxf(mx, __shfl_down_sync(0xffffffffu, mx, o));
    if ((tid & 31) == 0) sh[tid >> 5] = mx;
    __syncthreads();
    mx = fmaxf(fmaxf(sh[0], sh[1]), fmaxf(sh[2], sh[3]));
    __syncthreads();

    float sum = 0.f;
    for (int s = tid; s < len; s += 128) { float e = __expf(p[s] - mx); p[s] = e; sum += e; }
    #pragma unroll
    for (int o = 16; o; o >>= 1) sum += __shfl_down_sync(0xffffffffu, sum, o);
    if ((tid & 31) == 0) sh[tid >> 5] = sum;
    __syncthreads();
    sum = sh[0] + sh[1] + sh[2] + sh[3];
    float inv = 1.f / sum;
    for (int s = tid; s < len; s += 128) p[s] *= inv;
    for (int s = len + tid; s < T_; s += 128) p[s] = 0.f;
}

// O = P @ V ; skips K-tiles that are all-zero (s0 > t)
__global__ __launch_bounds__(256) void attn_pv_kernel(const float* __restrict__ qkv,
                                                      const float* __restrict__ P,
                                                      float* __restrict__ O) {
    int bh = blockIdx.y;
    int b = bh / H_, h = bh - b * H_;
    int t0 = blockIdx.x * 64;

    __shared__ float Ps[64][65];
    __shared__ float Vs[64][65];
    int tid = threadIdx.x;
    int ty = tid >> 4, tx = tid & 15;
    int tb = ty * 4, db = tx * 4;
    float acc[4][4] = {};
    const float* prow = P + ((size_t)bh * T_ + t0) * T_;

    for (int s0 = 0; s0 <= t0; s0 += 64) {
        #pragma unroll
        for (int l = 0; l < 16; l++) {
            int idx = tid + l * 256;
            int a_ = idx >> 6, b_ = idx & 63;
            Ps[b_][a_] = prow[(size_t)a_ * T_ + s0 + b_];
            Vs[a_][b_] = qkv[(size_t)(b * T_ + s0 + a_) * C3_ + 2 * C_ + h * HS_ + b_];
        }
        __syncthreads();
        #pragma unroll 16
        for (int s = 0; s < 64; s++) {
            float a0 = Ps[s][tb+0], a1 = Ps[s][tb+1], a2 = Ps[s][tb+2], a3 = Ps[s][tb+3];
            float b0 = Vs[s][db+0], b1 = Vs[s][db+1], b2 = Vs[s][db+2], b3 = Vs[s][db+3];
            acc[0][0]=fmaf(a0,b0,acc[0][0]); acc[0][1]=fmaf(a0,b1,acc[0][1]); acc[0][2]=fmaf(a0,b2,acc[0][2]); acc[0][3]=fmaf(a0,b3,acc[0][3]);
            acc[1][0]=fmaf(a1,b0,acc[1][0]); acc[1][1]=fmaf(a1,b1,acc[1][1]); acc[1][2]=fmaf(a1,b2,acc[1][2]); acc[1][3]=fmaf(a1,b3,acc[1][3]);
            acc[2][0]=fmaf(a2,b0,acc[2][0]); acc[2][1]=fmaf(a2,b1,acc[2][1]); acc[2][2]=fmaf(a2,b2,acc[2][2]); acc[2][3]=fmaf(a2,b3,acc[2][3]);
            acc[3][0]=fmaf(a3,b0,acc[3][0]); acc[3][1]=fmaf(a3,b1,acc[3][1]); acc[3][2]=fmaf(a3,b2,acc[3][2]); acc[3][3]=fmaf(a3,b3,acc[3][3]);
        }
        __syncthreads();
    }
    #pragma unroll
    for (int i = 0; i < 4; i++)
        #pragma unroll
        for (int j = 0; j < 4; j++)
            O[(size_t)(b * T_ + t0 + tb + i) * C_ + h * HS_ + db + j] = acc[i][j];
}

// ---------------- router: noisy top-2 + assignment (one warp / token) ----------------
__global__ __launch_bounds__(256) void router_kernel(
    const float* __restrict__ h2,
    const float* __restrict__ wr, const float* __restrict__ br,
    const float* __restrict__ wn, const float* __restrict__ bn,
    const float* __restrict__ noise, const float* __restrict__ temp_p,
    int* __restrict__ cnt, int* __restrict__ tok, float* __restrict__ gw)
{
    int n = blockIdx.x * 8 + (threadIdx.x >> 5);
    if (n >= N_) return;
    int lane = threadIdx.x & 31;
    float ar[E_] = {}, an[E_] = {};
    const float* hp = h2 + (size_t)n * C_;
    for (int c = lane; c < C_; c += 32) {
        float hv = hp[c];
        const float* wrp = wr + c * E_;
        const float* wnp = wn + c * E_;
        #pragma unroll
        for (int e = 0; e < E_; e++) {
            ar[e] = fmaf(hv, wrp[e], ar[e]);
            an[e] = fmaf(hv, wnp[e], an[e]);
        }
    }
    #pragma unroll
    for (int e = 0; e < E_; e++) {
        #pragma unroll
        for (int o = 16; o; o >>= 1) {
            ar[e] += __shfl_down_sync(0xffffffffu, ar[e], o);
            an[e] += __shfl_down_sync(0xffffffffu, an[e], o);
        }
    }
    if (lane == 0) {
        float t = fminf(fmaxf(*temp_p, 0.5f), 2.0f);
        float noisy[E_];
        #pragma unroll
        for (int e = 0; e < E_; e++) {
            float logit = ar[e] + br[e];
            float z = an[e] + bn[e];
            float sp = fmaxf(z, 0.f) + log1pf(expf(-fabsf(z)));
            noisy[e] = logit + t * noise[(size_t)n * E_ + e] * sp;
        }
        int i1 = 0;
        #pragma unroll
        for (int e = 1; e < E_; e++) if (noisy[e] > noisy[i1]) i1 = e;
        int i2 = -1;
        #pragma unroll
        for (int e = 0; e < E_; e++)
            if (e != i1 && (i2 < 0 || noisy[e] > noisy[i2])) i2 = e;
        float m = fmaxf(noisy[i1], noisy[i2]);
        float e1 = __expf(noisy[i1] - m), e2 = __expf(noisy[i2] - m);
        float inv = 1.f / (e1 + e2);
        int p1 = atomicAdd(&cnt[i1], 1); tok[i1 * N_ + p1] = n; gw[i1 * N_ + p1] = e1 * inv;
        int p2 = atomicAdd(&cnt[i2], 1); tok[i2 * N_ + p2] = n; gw[i2 * N_ + p2] = e2 * inv;
    }
}

// ---------------- expert epilogue: out[n] += gate * LN(h2[n] + Y[m]) ----------------
__global__ __launch_bounds__(256) void expert_epi_kernel(
    const float* __restrict__ Y, const float* __restrict__ h2,
    const int* __restrict__ tok, const float* __restrict__ gw,
    const int* __restrict__ cnt,
    const float* __restrict__ lg, const float* __restrict__ lb,
    float* __restrict__ out)
{
    int m = blockIdx.x;
    if (m >= *cnt) return;
    int n = tok[m];
    float g = gw[m];
    const float* yp = Y + (size_t)m * C_;
    const float* hp = h2 + (size_t)n * C_;
    int t = threadIdx.x;
    float z0 = hp[t]       + yp[t];
    float z1 = hp[t + 256] + yp[t + 256];
    float z2 = hp[t + 512] + yp[t + 512];
    float mean = blockReduceSum256(z0 + z1 + z2) * (1.0f / C_);
    float d0 = z0 - mean, d1 = z1 - mean, d2 = z2 - mean;
    float var = blockReduceSum256(d0*d0 + d1*d1 + d2*d2) * (1.0f / C_);
    float rstd = rsqrtf(var + 1e-5f);
    float* op = out + (size_t)n * C_;
    op[t]       += g * (d0 * rstd * lg[t]       + lb[t]);
    op[t + 256] += g * (d1 * rstd * lg[t + 256] + lb[t + 256]);
    op[t + 512] += g * (d2 * rstd * lg[t + 512] + lb[t + 512]);
}

// ---------------- launch ----------------
extern "C" void kernel_launch(void* const* d_in, const int* in_sizes, int n_in,
                              void* d_out, int out_size) {
    const float* x         = (const float*)d_in[0];
    const float* rnoise    = (const float*)d_in[1];
    const float* wq        = (const float*)d_in[2];
    const float* wk        = (const float*)d_in[3];
    const float* wv        = (const float*)d_in[4];
    const float* w_proj    = (const float*)d_in[5];
    const float* b_proj    = (const float*)d_in[6];
    const float* ln1_g     = (const float*)d_in[7];
    const float* ln1_b     = (const float*)d_in[8];
    const float* ln2_g     = (const float*)d_in[9];
    const float* ln2_b     = (const float*)d_in[10];
    const float* w_route   = (const float*)d_in[11];
    const float* b_route   = (const float*)d_in[12];
    const float* w_noise   = (const float*)d_in[13];
    const float* b_noise   = (const float*)d_in[14];
    const float* temp      = (const float*)d_in[15];
    const float* deep_w1   = (const float*)d_in[16];
    const float* deep_b1   = (const float*)d_in[17];
    const float* deep_w2   = (const float*)d_in[18];
    const float* deep_b2   = (const float*)d_in[19];
    const float* deep_w3   = (const float*)d_in[20];
    const float* deep_b3   = (const float*)d_in[21];
    const float* deep_ln_g = (const float*)d_in[22];
    const float* deep_ln_b = (const float*)d_in[23];
    const float* simple_w1   = (const float*)d_in[24];
    const float* simple_b1   = (const float*)d_in[25];
    const float* simple_w2   = (const float*)d_in[26];
    const float* simple_b2   = (const float*)d_in[27];
    const float* simple_ln_g = (const float*)d_in[28];
    const float* simple_ln_b = (const float*)d_in[29];

    float* out = (float*)d_out;

    float *h1, *qkv, *S, *o, *h2, *mid1, *mid2, *Y, *Wqkv, *gw;
    int *cnt, *tok;
    cudaGetSymbolAddress((void**)&h1,   g_h1);
    cudaGetSymbolAddress((void**)&qkv,  g_qkv);
    cudaGetSymbolAddress((void**)&S,    g_S);
    cudaGetSymbolAddress((void**)&o,    g_o);
    cudaGetSymbolAddress((void**)&h2,   g_h2);
    cudaGetSymbolAddress((void**)&mid1, g_mid1);
    cudaGetSymbolAddress((void**)&mid2, g_mid2);
    cudaGetSymbolAddress((void**)&Y,    g_Y);
    cudaGetSymbolAddress((void**)&Wqkv, g_Wqkv);
    cudaGetSymbolAddress((void**)&cnt,  g_cnt);
    cudaGetSymbolAddress((void**)&tok,  g_tok);
    cudaGetSymbolAddress((void**)&gw,   g_gw);

    zero_cnt_kernel<<<1, 32>>>(cnt);
    pack_wqkv_kernel<<<(C_ * C3_ + 255) / 256, 256>>>(wq, wk, wv);

    // ln1 -> h1 ; qkv = h1 @ Wqkv
    ln_kernel<<<N_, 256>>>(x, ln1_g, ln1_b, h1);
    tgemm_k<false, 0, false><<<dim3(C3_ / 128, N_ / 128), 256>>>(
        h1, C_, Wqkv, nullptr, nullptr, qkv, C3_, N_, C3_, C_, nullptr, nullptr);

    // attention
    attn_scores_kernel<<<dim3(T_ / 64, T_ / 64, BH_), 256>>>(qkv, S);
    softmax_causal_kernel<<<BH_ * T_, 128>>>(S);
    attn_pv_kernel<<<dim3(T_ / 64, BH_), 256>>>(qkv, S, o);

    // out = x + o @ w_proj + b_proj   (out also serves as residual base x1)
    tgemm_k<false, 0, true><<<dim3(C_ / 128, N_ / 128), 256>>>(
        o, C_, w_proj, b_proj, x, out, C_, N_, C_, C_, nullptr, nullptr);

    // ln2 -> h2 ; router + token assignment
    ln_kernel<<<N_, 256>>>(out, ln2_g, ln2_b, h2);
    router_kernel<<<N_ / 8, 256>>>(h2, w_route, b_route, w_noise, b_noise,
                                   rnoise, temp, cnt, tok, gw);

    // deep experts (0..1): gelu(W1) -> gelu(W2) -> W3 -> LN accumulate
    for (int e = 0; e < 2; e++) {
        const int*   ce = cnt + e;
        const int*   te = tok + e * N_;
        const float* ge = gw + e * N_;
        tgemm_k<true, 1, false><<<dim3(F_ / 128, N_ / 128), 256>>>(
            h2, C_, deep_w1 + (size_t)e * C_ * F_, deep_b1 + (size_t)e * F_,
            nullptr, mid1, F_, N_, F_, C_, te, ce);
        tgemm_k<false, 1, false><<<dim3(F_ / 128, N_ / 128), 256>>>(
            mid1, F_, deep_w2 + (size_t)e * F_ * F_, deep_b2 + (size_t)e * F_,
            nullptr, mid2, F_, N_, F_, F_, nullptr, ce);
        tgemm_k<false, 0, false><<<dim3(C_ / 128, N_ / 128), 256>>>(
            mid2, F_, deep_w3 + (size_t)e * F_ * C_, deep_b3 + (size_t)e * C_,
            nullptr, Y, C_, N_, C_, F_, nullptr, ce);
        expert_epi_kernel<<<N_, 256>>>(Y, h2, te, ge, ce,
                                       deep_ln_g + (size_t)e * C_,
                                       deep_ln_b + (size_t)e * C_, out);
    }

    // simple experts (2..7): gelu(W1) -> W2 -> LN accumulate
    for (int e = 0; e < 6; e++) {
        int ee = 2 + e;
        const int*   ce = cnt + ee;
        const int*   te = tok + ee * N_;
        const float* ge = gw + ee * N_;
        tgemm_k<true, 1, false><<<dim3(F_ / 128, N_ / 128), 256>>>(
            h2, C_, simple_w1 + (size_t)e * C_ * F_, simple_b1 + (size_t)e * F_,
            nullptr, mid1, F_, N_, F_, C_, te, ce);
        tgemm_k<false, 0, false><<<dim3(C_ / 128, N_ / 128), 256>>>(
            mid1, F_, simple_w2 + (size_t)e * F_ * C_, simple_b2 + (size_t)e * C_,
            nullptr, Y, C_, N_, C_, F_, nullptr, ce);
        expert_epi_kernel<<<N_, 256>>>(Y, h2, te, ge, ce,
                                       simple_ln_g + (size_t)e * C_,
                                       simple_ln_b + (size_t)e * C_, out);
    }
}

// round 10
// speedup vs baseline: 2.4264x; 1.0026x over previous
#include <cuda_runtime.h>
#include <math.h>

// ---------------- problem constants ----------------
#define B_   8
#define T_   1024
#define C_   768
#define H_   12
#define HS_  64
#define E_   8
#define F_   3072
#define N_   (B_*T_)     // 8192 tokens
#define BH_  (B_*H_)     // 96
#define C3_  (3*C_)      // 2304

// ---------------- scratch (device globals; no allocation) ----------------
__device__ float g_h1  [N_*C_];
__device__ float g_qkv [N_*C3_];
__device__ float g_S   [(size_t)BH_*T_*T_];   // 402 MB scores/probs (in-place softmax)
__device__ float g_o   [N_*C_];
__device__ float g_h2  [N_*C_];
__device__ float g_mid1[N_*F_];
__device__ float g_mid2[N_*F_];
__device__ float g_Y   [N_*C_];
__device__ float g_Wqkv[C_*C3_];
__device__ int   g_cnt [E_];
__device__ int   g_tok [E_*N_];
__device__ float g_gw  [E_*N_];

// ---------------- helpers ----------------
__device__ __forceinline__ float gelu_f(float z) {
    return 0.5f * z * (1.0f + erff(z * 0.70710678118654752440f));
}

__device__ __forceinline__ unsigned f2tf32(float f) {
    unsigned r;
    asm("cvt.rna.tf32.f32 %0, %1;" : "=r"(r) : "f"(f));
    return r;
}

__device__ __forceinline__ void ldsm4(unsigned &r0, unsigned &r1, unsigned &r2, unsigned &r3,
                                      const unsigned* p) {
    unsigned addr = (unsigned)__cvta_generic_to_shared(p);
    asm volatile("ldmatrix.sync.aligned.m8n8.x4.shared.b16 {%0,%1,%2,%3}, [%4];"
        : "=r"(r0), "=r"(r1), "=r"(r2), "=r"(r3) : "r"(addr));
}

__device__ __forceinline__ void mma_tf32(float* c, const unsigned* a, const unsigned* b) {
    asm volatile("mma.sync.aligned.m16n8k8.row.col.f32.tf32.tf32.f32 "
        "{%0,%1,%2,%3}, {%4,%5,%6,%7}, {%8,%9}, {%0,%1,%2,%3};"
        : "+f"(c[0]), "+f"(c[1]), "+f"(c[2]), "+f"(c[3])
        : "r"(a[0]), "r"(a[1]), "r"(a[2]), "r"(a[3]), "r"(b[0]), "r"(b[1]));
}

// block-wide sum for 256 threads (8 warps)
__device__ __forceinline__ float blockReduceSum256(float v) {
    __shared__ float sh[8];
    int lane = threadIdx.x & 31, w = threadIdx.x >> 5;
    #pragma unroll
    for (int o = 16; o; o >>= 1) v += __shfl_down_sync(0xffffffffu, v, o);
    if (lane == 0) sh[w] = v;
    __syncthreads();
    float r;
    if (w == 0) {
        float t = (lane < 8) ? sh[lane] : 0.f;
        #pragma unroll
        for (int o = 4; o; o >>= 1) t += __shfl_down_sync(0xffffffffu, t, o);
        if (lane == 0) sh[0] = t;
    }
    __syncthreads();
    r = sh[0];
    __syncthreads();
    return r;
}

// ---------------- small setup kernels ----------------
__global__ void zero_cnt_kernel(int* cnt) {
    if (threadIdx.x < E_) cnt[threadIdx.x] = 0;
}

// pack wq,wk,wv (H,C,HS) -> Wqkv[C][3C] with col = which*C + h*HS + d
__global__ void pack_wqkv_kernel(const float* __restrict__ wq,
                                 const float* __restrict__ wk,
                                 const float* __restrict__ wv) {
    int idx = blockIdx.x * 256 + threadIdx.x;
    if (idx >= C_ * C3_) return;
    int c   = idx / C3_;
    int col = idx - c * C3_;
    int which = col / C_;
    int rem   = col - which * C_;
    int h = rem / HS_;
    int d = rem - h * HS_;
    const float* w = (which == 0) ? wq : ((which == 1) ? wk : wv);
    g_Wqkv[idx] = w[(h * C_ + c) * HS_ + d];
}

// LayerNorm over C=768 (one row per block, 256 threads x 3 elems)
__global__ __launch_bounds__(256) void ln_kernel(const float* __restrict__ in,
                                                 const float* __restrict__ g,
                                                 const float* __restrict__ b,
                                                 float* __restrict__ out) {
    int row = blockIdx.x;
    const float* p = in + (size_t)row * C_;
    int t = threadIdx.x;
    float x0 = p[t], x1 = p[t + 256], x2 = p[t + 512];
    float mean = blockReduceSum256(x0 + x1 + x2) * (1.0f / C_);
    float d0 = x0 - mean, d1 = x1 - mean, d2 = x2 - mean;
    float var = blockReduceSum256(d0*d0 + d1*d1 + d2*d2) * (1.0f / C_);
    float rstd = rsqrtf(var + 1e-5f);
    float* o = out + (size_t)row * C_;
    o[t]       = d0 * rstd * g[t]       + b[t];
    o[t + 256] = d1 * rstd * g[t + 256] + b[t + 256];
    o[t + 512] = d2 * rstd * g[t + 512] + b[t + 512];
}

// ---------------- tf32 tensor-core GEMM ----------------
// C[m,n] = act(A[m,:] @ B[:,n] + bias[n]) (+ resid[m,n])
// Block tile 128x128x16, 8 warps (2x4), warp tile 64x32 via mma.m16n8k8 tf32.
// GATHER: A row index from rows[m]; cntPtr (if non-null) overrides M.
// Requires Nn % 128 == 0, Kk % 16 == 0.
template<bool GATHER, int ACT, bool RESID>
__global__ __launch_bounds__(256) void tgemm_k(
    const float* __restrict__ A, int lda,
    const float* __restrict__ Bm,
    const float* __restrict__ bias,
    const float* __restrict__ resid,
    float* __restrict__ Cm, int ldc,
    int M, int Nn, int Kk,
    const int* __restrict__ rows,
    const int* __restrict__ cntPtr)
{
    if (cntPtr) M = *cntPtr;
    int m0 = blockIdx.y * 128;
    if (m0 >= M) return;
    int n0 = blockIdx.x * 128;

    __shared__ unsigned As[2][128][20];   // [row][k], pad 20 -> conflict-free ldsm
    __shared__ unsigned Bs[2][16][136];   // [k][n],  pad 136 -> conflict-free LDS
    __shared__ int rIdx[128];

    int tid = threadIdx.x;
    if (GATHER) {
        if (tid < 128) {
            int m = m0 + tid;
            rIdx[tid] = rows[(m < M) ? m : (M - 1)];
        }
        __syncthreads();
    }

    // ---- gmem load mapping ----
    // A: thread loads row (tid&127), two float4 at k-cols aCol and aCol+8
    int aRow = tid & 127;
    int aCol = (tid >> 7) * 4;   // 0 or 4
    int aSrcRow;
    if (GATHER) aSrcRow = rIdx[aRow];
    else { int gm = m0 + aRow; aSrcRow = (gm < M) ? gm : (M - 1); }
    const float* aPtr = A + (size_t)aSrcRow * lda;
    // B: thread loads k-row (tid>>4), two float4 at n-cols bN and bN+64
    int bK = tid >> 4;
    int bN = (tid & 15) * 4;
    const float* bPtr = Bm + (size_t)bK * Nn + n0;

    float4 aV0, aV1, bV0, bV1;

    // ---- warp / fragment mapping ----
    int wid = tid >> 5, lane = tid & 31;
    int warpM = (wid >> 2) * 64;     // 0 or 64
    int warpN = (wid & 3) * 32;      // 0,32,64,96
    int g  = lane >> 2;              // groupID 0..7
    int tg = lane & 3;               // thread-in-group 0..3
    // per-thread ldmatrix address components (x4 tile decomposition)
    int aRowIn = ((lane >> 3) & 1) * 8 + (lane & 7);
    int aColIn = ((lane >> 3) >> 1) * 4;

    float acc[4][4][4];
    #pragma unroll
    for (int i = 0; i < 4; i++)
        #pragma unroll
        for (int j = 0; j < 4; j++)
            #pragma unroll
            for (int r = 0; r < 4; r++) acc[i][j][r] = 0.f;

    int nTiles = Kk / 16;

    // prologue: load tile 0 and stage it
    aV0 = *(const float4*)(aPtr + 0 + aCol);
    aV1 = *(const float4*)(aPtr + 0 + aCol + 8);
    bV0 = *(const float4*)(bPtr + 0 + bN);
    bV1 = *(const float4*)(bPtr + 0 + bN + 64);
    {
        uint4 u0 = { f2tf32(aV0.x), f2tf32(aV0.y), f2tf32(aV0.z), f2tf32(aV0.w) };
        uint4 u1 = { f2tf32(aV1.x), f2tf32(aV1.y), f2tf32(aV1.z), f2tf32(aV1.w) };
        *(uint4*)&As[0][aRow][aCol]     = u0;
        *(uint4*)&As[0][aRow][aCol + 8] = u1;
        uint4 v0 = { f2tf32(bV0.x), f2tf32(bV0.y), f2tf32(bV0.z), f2tf32(bV0.w) };
        uint4 v1 = { f2tf32(bV1.x), f2tf32(bV1.y), f2tf32(bV1.z), f2tf32(bV1.w) };
        *(uint4*)&Bs[0][bK][bN]      = v0;
        *(uint4*)&Bs[0][bK][bN + 64] = v1;
    }
    __syncthreads();

    for (int t = 0; t < nTiles; t++) {
        int buf = t & 1;
        bool more = (t + 1 < nTiles);
        if (more) {
            int k0 = (t + 1) * 16;
            aV0 = *(const float4*)(aPtr + k0 + aCol);
            aV1 = *(const float4*)(aPtr + k0 + aCol + 8);
            const float* bp = bPtr + (size_t)k0 * Nn;
            bV0 = *(const float4*)(bp + bN);
            bV1 = *(const float4*)(bp + bN + 64);
        }

        #pragma unroll
        for (int s = 0; s < 2; s++) {
            unsigned af[4][4];
            #pragma unroll
            for (int i = 0; i < 4; i++)
                ldsm4(af[i][0], af[i][1], af[i][2], af[i][3],
                      &As[buf][warpM + i * 16 + aRowIn][s * 8 + aColIn]);
            unsigned bf[4][2];
            #pragma unroll
            for (int j = 0; j < 4; j++) {
                int col = warpN + j * 8 + g;
                bf[j][0] = Bs[buf][s * 8 + tg][col];
                bf[j][1] = Bs[buf][s * 8 + tg + 4][col];
            }
            #pragma unroll
            for (int i = 0; i < 4; i++)
                #pragma unroll
                for (int j = 0; j < 4; j++)
                    mma_tf32(acc[i][j], af[i], bf[j]);
        }

        if (more) {
            int nb = buf ^ 1;
            uint4 u0 = { f2tf32(aV0.x), f2tf32(aV0.y), f2tf32(aV0.z), f2tf32(aV0.w) };
            uint4 u1 = { f2tf32(aV1.x), f2tf32(aV1.y), f2tf32(aV1.z), f2tf32(aV1.w) };
            *(uint4*)&As[nb][aRow][aCol]     = u0;
            *(uint4*)&As[nb][aRow][aCol + 8] = u1;
            uint4 v0 = { f2tf32(bV0.x), f2tf32(bV0.y), f2tf32(bV0.z), f2tf32(bV0.w) };
            uint4 v1 = { f2tf32(bV1.x), f2tf32(bV1.y), f2tf32(bV1.z), f2tf32(bV1.w) };
            *(uint4*)&Bs[nb][bK][bN]      = v0;
            *(uint4*)&Bs[nb][bK][bN + 64] = v1;
        }
        __syncthreads();
    }

    // ---- epilogue ----
    #pragma unroll
    for (int i = 0; i < 4; i++) {
        int r0 = m0 + warpM + i * 16 + g;
        int r1 = r0 + 8;
        #pragma unroll
        for (int j = 0; j < 4; j++) {
            int col = n0 + warpN + j * 8 + tg * 2;
            float b0 = 0.f, b1 = 0.f;
            if (bias) { b0 = bias[col]; b1 = bias[col + 1]; }
            if (r0 < M) {
                float v0 = acc[i][j][0] + b0;
                float v1 = acc[i][j][1] + b1;
                if (ACT == 1) { v0 = gelu_f(v0); v1 = gelu_f(v1); }
                if (RESID) {
                    v0 += resid[(size_t)r0 * ldc + col];
                    v1 += resid[(size_t)r0 * ldc + col + 1];
                }
                *(float2*)&Cm[(size_t)r0 * ldc + col] = make_float2(v0, v1);
            }
            if (r1 < M) {
                float v2 = acc[i][j][2] + b0;
                float v3 = acc[i][j][3] + b1;
                if (ACT == 1) { v2 = gelu_f(v2); v3 = gelu_f(v3); }
                if (RESID) {
                    v2 += resid[(size_t)r1 * ldc + col];
                    v3 += resid[(size_t)r1 * ldc + col + 1];
                }
                *(float2*)&Cm[(size_t)r1 * ldc + col] = make_float2(v2, v3);
            }
        }
    }
}

// ---------------- attention ----------------
// raw scores S[bh][t][s] = (q.k) * C^-0.5 ; skip fully-masked tiles
__global__ __launch_bounds__(256) void attn_scores_kernel(const float* __restrict__ qkv,
                                                          float* __restrict__ S) {
    int bh = blockIdx.z;
    int t0 = blockIdx.y * 64, s0 = blockIdx.x * 64;
    if (s0 > t0) return;
    int b = bh / H_, h = bh - b * H_;

    __shared__ float Qs[64][65];
    __shared__ float Ks[64][65];
    int tid = threadIdx.x;
    const float* qb = qkv + (size_t)(b * T_ + t0) * C3_ + h * HS_;
    const float* kb = qkv + (size_t)(b * T_ + s0) * C3_ + C_ + h * HS_;
    #pragma unroll
    for (int l = 0; l < 16; l++) {
        int idx = tid + l * 256;
        int r = idx >> 6, d = idx & 63;
        Qs[d][r] = qb[(size_t)r * C3_ + d];
        Ks[d][r] = kb[(size_t)r * C3_ + d];
    }
    __syncthreads();

    int ty = tid >> 4, tx = tid & 15;
    int tb = ty * 4, sb = tx * 4;
    float acc[4][4] = {};
    #pragma unroll 16
    for (int d = 0; d < 64; d++) {
        float a0 = Qs[d][tb+0], a1 = Qs[d][tb+1], a2 = Qs[d][tb+2], a3 = Qs[d][tb+3];
        float b0 = Ks[d][sb+0], b1 = Ks[d][sb+1], b2 = Ks[d][sb+2], b3 = Ks[d][sb+3];
        acc[0][0]=fmaf(a0,b0,acc[0][0]); acc[0][1]=fmaf(a0,b1,acc[0][1]); acc[0][2]=fmaf(a0,b2,acc[0][2]); acc[0][3]=fmaf(a0,b3,acc[0][3]);
        acc[1][0]=fmaf(a1,b0,acc[1][0]); acc[1][1]=fmaf(a1,b1,acc[1][1]); acc[1][2]=fmaf(a1,b2,acc[1][2]); acc[1][3]=fmaf(a1,b3,acc[1][3]);
        acc[2][0]=fmaf(a2,b0,acc[2][0]); acc[2][1]=fmaf(a2,b1,acc[2][1]); acc[2][2]=fmaf(a2,b2,acc[2][2]); acc[2][3]=fmaf(a2,b3,acc[2][3]);
        acc[3][0]=fmaf(a3,b0,acc[3][0]); acc[3][1]=fmaf(a3,b1,acc[3][1]); acc[3][2]=fmaf(a3,b2,acc[3][2]); acc[3][3]=fmaf(a3,b3,acc[3][3]);
    }
    const float scale = 0.03608439182435161f;   // 768^-0.5
    float* op = S + ((size_t)bh * T_ + t0) * T_ + s0;
    #pragma unroll
    for (int i = 0; i < 4; i++)
        #pragma unroll
        for (int j = 0; j < 4; j++)
            op[(size_t)(tb + i) * T_ + sb + j] = acc[i][j] * scale;
}

// causal softmax in place: reads only s<=t, zeros s>t
__global__ __launch_bounds__(128) void softmax_causal_kernel(float* __restrict__ S) {
    int row = blockIdx.x;
    int t = row & (T_ - 1);
    float* p = S + (size_t)row * T_;
    int len = t + 1;
    int tid = threadIdx.x;
    __shared__ float sh[4];

    float mx = -1e30f;
    for (int s = tid; s < len; s += 128) mx = fmaxf(mx, p[s]);
    #pragma unroll
    for (int o = 16; o; o >>= 1) mx = fmaxf(mx, __shfl_down_sync(0xffffffffu, mx, o));
    if ((tid & 31) == 0) sh[tid >> 5] = mx;
    __syncthreads();
    mx = fmaxf(fmaxf(sh[0], sh[1]), fmaxf(sh[2], sh[3]));
    __syncthreads();

    float sum = 0.f;
    for (int s = tid; s < len; s += 128) { float e = __expf(p[s] - mx); p[s] = e; sum += e; }
    #pragma unroll
    for (int o = 16; o; o >>= 1) sum += __shfl_down_sync(0xffffffffu, sum, o);
    if ((tid & 31) == 0) sh[tid >> 5] = sum;
    __syncthreads();
    sum = sh[0] + sh[1] + sh[2] + sh[3];
    float inv = 1.f / sum;
    for (int s = tid; s < len; s += 128) p[s] *= inv;
    for (int s = len + tid; s < T_; s += 128) p[s] = 0.f;
}

// O = P @ V ; skips K-tiles that are all-zero (s0 > t)
__global__ __launch_bounds__(256) void attn_pv_kernel(const float* __restrict__ qkv,
                                                      const float* __restrict__ P,
                                                      float* __restrict__ O) {
    int bh = blockIdx.y;
    int b = bh / H_, h = bh - b * H_;
    int t0 = blockIdx.x * 64;

    __shared__ float Ps[64][65];
    __shared__ float Vs[64][65];
    int tid = threadIdx.x;
    int ty = tid >> 4, tx = tid & 15;
    int tb = ty * 4, db = tx * 4;
    float acc[4][4] = {};
    const float* prow = P + ((size_t)bh * T_ + t0) * T_;

    for (int s0 = 0; s0 <= t0; s0 += 64) {
        #pragma unroll
        for (int l = 0; l < 16; l++) {
            int idx = tid + l * 256;
            int a_ = idx >> 6, b_ = idx & 63;
            Ps[b_][a_] = prow[(size_t)a_ * T_ + s0 + b_];
            Vs[a_][b_] = qkv[(size_t)(b * T_ + s0 + a_) * C3_ + 2 * C_ + h * HS_ + b_];
        }
        __syncthreads();
        #pragma unroll 16
        for (int s = 0; s < 64; s++) {
            float a0 = Ps[s][tb+0], a1 = Ps[s][tb+1], a2 = Ps[s][tb+2], a3 = Ps[s][tb+3];
            float b0 = Vs[s][db+0], b1 = Vs[s][db+1], b2 = Vs[s][db+2], b3 = Vs[s][db+3];
            acc[0][0]=fmaf(a0,b0,acc[0][0]); acc[0][1]=fmaf(a0,b1,acc[0][1]); acc[0][2]=fmaf(a0,b2,acc[0][2]); acc[0][3]=fmaf(a0,b3,acc[0][3]);
            acc[1][0]=fmaf(a1,b0,acc[1][0]); acc[1][1]=fmaf(a1,b1,acc[1][1]); acc[1][2]=fmaf(a1,b2,acc[1][2]); acc[1][3]=fmaf(a1,b3,acc[1][3]);
            acc[2][0]=fmaf(a2,b0,acc[2][0]); acc[2][1]=fmaf(a2,b1,acc[2][1]); acc[2][2]=fmaf(a2,b2,acc[2][2]); acc[2][3]=fmaf(a2,b3,acc[2][3]);
            acc[3][0]=fmaf(a3,b0,acc[3][0]); acc[3][1]=fmaf(a3,b1,acc[3][1]); acc[3][2]=fmaf(a3,b2,acc[3][2]); acc[3][3]=fmaf(a3,b3,acc[3][3]);
        }
        __syncthreads();
    }
    #pragma unroll
    for (int i = 0; i < 4; i++)
        #pragma unroll
        for (int j = 0; j < 4; j++)
            O[(size_t)(b * T_ + t0 + tb + i) * C_ + h * HS_ + db + j] = acc[i][j];
}

// ---------------- router: noisy top-2 + assignment (one warp / token) ----------------
__global__ __launch_bounds__(256) void router_kernel(
    const float* __restrict__ h2,
    const float* __restrict__ wr, const float* __restrict__ br,
    const float* __restrict__ wn, const float* __restrict__ bn,
    const float* __restrict__ noise, const float* __restrict__ temp_p,
    int* __restrict__ cnt, int* __restrict__ tok, float* __restrict__ gw)
{
    int n = blockIdx.x * 8 + (threadIdx.x >> 5);
    if (n >= N_) return;
    int lane = threadIdx.x & 31;
    float ar[E_] = {}, an[E_] = {};
    const float* hp = h2 + (size_t)n * C_;
    for (int c = lane; c < C_; c += 32) {
        float hv = hp[c];
        const float* wrp = wr + c * E_;
        const float* wnp = wn + c * E_;
        #pragma unroll
        for (int e = 0; e < E_; e++) {
            ar[e] = fmaf(hv, wrp[e], ar[e]);
            an[e] = fmaf(hv, wnp[e], an[e]);
        }
    }
    #pragma unroll
    for (int e = 0; e < E_; e++) {
        #pragma unroll
        for (int o = 16; o; o >>= 1) {
            ar[e] += __shfl_down_sync(0xffffffffu, ar[e], o);
            an[e] += __shfl_down_sync(0xffffffffu, an[e], o);
        }
    }
    if (lane == 0) {
        float t = fminf(fmaxf(*temp_p, 0.5f), 2.0f);
        float noisy[E_];
        #pragma unroll
        for (int e = 0; e < E_; e++) {
            float logit = ar[e] + br[e];
            float z = an[e] + bn[e];
            float sp = fmaxf(z, 0.f) + log1pf(expf(-fabsf(z)));
            noisy[e] = logit + t * noise[(size_t)n * E_ + e] * sp;
        }
        int i1 = 0;
        #pragma unroll
        for (int e = 1; e < E_; e++) if (noisy[e] > noisy[i1]) i1 = e;
        int i2 = -1;
        #pragma unroll
        for (int e = 0; e < E_; e++)
            if (e != i1 && (i2 < 0 || noisy[e] > noisy[i2])) i2 = e;
        float m = fmaxf(noisy[i1], noisy[i2]);
        float e1 = __expf(noisy[i1] - m), e2 = __expf(noisy[i2] - m);
        float inv = 1.f / (e1 + e2);
        int p1 = atomicAdd(&cnt[i1], 1); tok[i1 * N_ + p1] = n; gw[i1 * N_ + p1] = e1 * inv;
        int p2 = atomicAdd(&cnt[i2], 1); tok[i2 * N_ + p2] = n; gw[i2 * N_ + p2] = e2 * inv;
    }
}

// ---------------- expert epilogue: out[n] += gate * LN(h2[n] + Y[m]) ----------------
__global__ __launch_bounds__(256) void expert_epi_kernel(
    const float* __restrict__ Y, const float* __restrict__ h2,
    const int* __restrict__ tok, const float* __restrict__ gw,
    const int* __restrict__ cnt,
    const float* __restrict__ lg, const float* __restrict__ lb,
    float* __restrict__ out)
{
    int m = blockIdx.x;
    if (m >= *cnt) return;
    int n = tok[m];
    float g = gw[m];
    const float* yp = Y + (size_t)m * C_;
    const float* hp = h2 + (size_t)n * C_;
    int t = threadIdx.x;
    float z0 = hp[t]       + yp[t];
    float z1 = hp[t + 256] + yp[t + 256];
    float z2 = hp[t + 512] + yp[t + 512];
    float mean = blockReduceSum256(z0 + z1 + z2) * (1.0f / C_);
    float d0 = z0 - mean, d1 = z1 - mean, d2 = z2 - mean;
    float var = blockReduceSum256(d0*d0 + d1*d1 + d2*d2) * (1.0f / C_);
    float rstd = rsqrtf(var + 1e-5f);
    float* op = out + (size_t)n * C_;
    op[t]       += g * (d0 * rstd * lg[t]       + lb[t]);
    op[t + 256] += g * (d1 * rstd * lg[t + 256] + lb[t + 256]);
    op[t + 512] += g * (d2 * rstd * lg[t + 512] + lb[t + 512]);
}

// ---------------- launch ----------------
extern "C" void kernel_launch(void* const* d_in, const int* in_sizes, int n_in,
                              void* d_out, int out_size) {
    const float* x         = (const float*)d_in[0];
    const float* rnoise    = (const float*)d_in[1];
    const float* wq        = (const float*)d_in[2];
    const float* wk        = (const float*)d_in[3];
    const float* wv        = (const float*)d_in[4];
    const float* w_proj    = (const float*)d_in[5];
    const float* b_proj    = (const float*)d_in[6];
    const float* ln1_g     = (const float*)d_in[7];
    const float* ln1_b     = (const float*)d_in[8];
    const float* ln2_g     = (const float*)d_in[9];
    const float* ln2_b     = (const float*)d_in[10];
    const float* w_route   = (const float*)d_in[11];
    const float* b_route   = (const float*)d_in[12];
    const float* w_noise   = (const float*)d_in[13];
    const float* b_noise   = (const float*)d_in[14];
    const float* temp      = (const float*)d_in[15];
    const float* deep_w1   = (const float*)d_in[16];
    const float* deep_b1   = (const float*)d_in[17];
    const float* deep_w2   = (const float*)d_in[18];
    const float* deep_b2   = (const float*)d_in[19];
    const float* deep_w3   = (const float*)d_in[20];
    const float* deep_b3   = (const float*)d_in[21];
    const float* deep_ln_g = (const float*)d_in[22];
    const float* deep_ln_b = (const float*)d_in[23];
    const float* simple_w1   = (const float*)d_in[24];
    const float* simple_b1   = (const float*)d_in[25];
    const float* simple_w2   = (const float*)d_in[26];
    const float* simple_b2   = (const float*)d_in[27];
    const float* simple_ln_g = (const float*)d_in[28];
    const float* simple_ln_b = (const float*)d_in[29];

    float* out = (float*)d_out;

    float *h1, *qkv, *S, *o, *h2, *mid1, *mid2, *Y, *Wqkv, *gw;
    int *cnt, *tok;
    cudaGetSymbolAddress((void**)&h1,   g_h1);
    cudaGetSymbolAddress((void**)&qkv,  g_qkv);
    cudaGetSymbolAddress((void**)&S,    g_S);
    cudaGetSymbolAddress((void**)&o,    g_o);
    cudaGetSymbolAddress((void**)&h2,   g_h2);
    cudaGetSymbolAddress((void**)&mid1, g_mid1);
    cudaGetSymbolAddress((void**)&mid2, g_mid2);
    cudaGetSymbolAddress((void**)&Y,    g_Y);
    cudaGetSymbolAddress((void**)&Wqkv, g_Wqkv);
    cudaGetSymbolAddress((void**)&cnt,  g_cnt);
    cudaGetSymbolAddress((void**)&tok,  g_tok);
    cudaGetSymbolAddress((void**)&gw,   g_gw);

    zero_cnt_kernel<<<1, 32>>>(cnt);
    pack_wqkv_kernel<<<(C_ * C3_ + 255) / 256, 256>>>(wq, wk, wv);

    // ln1 -> h1 ; qkv = h1 @ Wqkv
    ln_kernel<<<N_, 256>>>(x, ln1_g, ln1_b, h1);
    tgemm_k<false, 0, false><<<dim3(C3_ / 128, N_ / 128), 256>>>(
        h1, C_, Wqkv, nullptr, nullptr, qkv, C3_, N_, C3_, C_, nullptr, nullptr);

    // attention
    attn_scores_kernel<<<dim3(T_ / 64, T_ / 64, BH_), 256>>>(qkv, S);
    softmax_causal_kernel<<<BH_ * T_, 128>>>(S);
    attn_pv_kernel<<<dim3(T_ / 64, BH_), 256>>>(qkv, S, o);

    // out = x + o @ w_proj + b_proj   (out also serves as residual base x1)
    tgemm_k<false, 0, true><<<dim3(C_ / 128, N_ / 128), 256>>>(
        o, C_, w_proj, b_proj, x, out, C_, N_, C_, C_, nullptr, nullptr);

    // ln2 -> h2 ; router + token assignment
    ln_kernel<<<N_, 256>>>(out, ln2_g, ln2_b, h2);
    router_kernel<<<N_ / 8, 256>>>(h2, w_route, b_route, w_noise, b_noise,
                                   rnoise, temp, cnt, tok, gw);

    // deep experts (0..1): gelu(W1) -> gelu(W2) -> W3 -> LN accumulate
    for (int e = 0; e < 2; e++) {
        const int*   ce = cnt + e;
        const int*   te = tok + e * N_;
        const float* ge = gw + e * N_;
        tgemm_k<true, 1, false><<<dim3(F_ / 128, N_ / 128), 256>>>(
            h2, C_, deep_w1 + (size_t)e * C_ * F_, deep_b1 + (size_t)e * F_,
            nullptr, mid1, F_, N_, F_, C_, te, ce);
        tgemm_k<false, 1, false><<<dim3(F_ / 128, N_ / 128), 256>>>(
            mid1, F_, deep_w2 + (size_t)e * F_ * F_, deep_b2 + (size_t)e * F_,
            nullptr, mid2, F_, N_, F_, F_, nullptr, ce);
        tgemm_k<false, 0, false><<<dim3(C_ / 128, N_ / 128), 256>>>(
            mid2, F_, deep_w3 + (size_t)e * F_ * C_, deep_b3 + (size_t)e * C_,
            nullptr, Y, C_, N_, C_, F_, nullptr, ce);
        expert_epi_kernel<<<N_, 256>>>(Y, h2, te, ge, ce,
                                       deep_ln_g + (size_t)e * C_,
                                       deep_ln_b + (size_t)e * C_, out);
    }

    // simple experts (2..7): gelu(W1) -> W2 -> LN accumulate
    for (int e = 0; e < 6; e++) {
        int ee = 2 + e;
        const int*   ce = cnt + ee;
        const int*   te = tok + ee * N_;
        const float* ge = gw + ee * N_;
        tgemm_k<true, 1, false><<<dim3(F_ / 128, N_ / 128), 256>>>(
            h2, C_, simple_w1 + (size_t)e * C_ * F_, simple_b1 + (size_t)e * F_,
            nullptr, mid1, F_, N_, F_, C_, te, ce);
        tgemm_k<false, 0, false><<<dim3(C_ / 128, N_ / 128), 256>>>(
            mid1, F_, simple_w2 + (size_t)e * F_ * C_, simple_b2 + (size_t)e * C_,
            nullptr, Y, C_, N_, C_, F_, nullptr, ce);
        expert_epi_kernel<<<N_, 256>>>(Y, h2, te, ge, ce,
                                       simple_ln_g + (size_t)e * C_,
                                       simple_ln_b + (size_t)e * C_, out);
    }
}